// round 5
// baseline (speedup 1.0000x reference)
#include <cuda_runtime.h>
#include <math.h>
#include <stdint.h>

// Problem constants
#define BB 2
#define SS 2048
#define DD 768
#define HH 12
#define HDIM 64
#define NT (BB*SS)      // 4096 tokens
#define NBH (BB*HH)     // 24

typedef unsigned long long u64;

// ---------------------------------------------------------------------------
// f32x2 packed helpers (PTX ISA 8.6+, sm_100 family baseline)
// ---------------------------------------------------------------------------
__device__ __forceinline__ u64 pk2(float lo, float hi) {
    u64 r; asm("mov.b64 %0, {%1, %2};" : "=l"(r) : "f"(lo), "f"(hi)); return r;
}
__device__ __forceinline__ float2 up2(u64 v) {
    float lo, hi; asm("mov.b64 {%0, %1}, %2;" : "=f"(lo), "=f"(hi) : "l"(v));
    return make_float2(lo, hi);
}
__device__ __forceinline__ void fma2(u64& d, u64 a, u64 b) {
    asm("fma.rn.f32x2 %0, %1, %2, %0;" : "+l"(d) : "l"(a), "l"(b));
}
__device__ __forceinline__ void mul2(u64& d, u64 a) {
    asm("mul.rn.f32x2 %0, %0, %1;" : "+l"(d) : "l"(a));
}

// ---------------------------------------------------------------------------
// Device scratch
// ---------------------------------------------------------------------------
__device__ float g_q[(size_t)NT * DD];        // [b,s,d]
__device__ float g_k[(size_t)NT * DD];
__device__ float g_v[(size_t)NT * DD];
__device__ float g_att[(size_t)NT * DD];

// ---------------------------------------------------------------------------
// FFMA2 GEMM: out[m,n] = sum_k A[m,k]*W[k,n] + bias[n]
// CTA tile 128x128, K-tile 16, 256 threads, 8x8 per-thread microtile.
// Accumulators are f32x2 pairs along N (pairs natural from smem ulonglong2).
// ---------------------------------------------------------------------------
#define TM 128
#define TN 128
#define TKK 16
#define SP 132                 // smem pitch (floats); row stride 528B = 16B-mult
#define NKT (DD / TKK)         // 48

__global__ __launch_bounds__(256, 2)
void gemm_f2(const float* __restrict__ A, const float* __restrict__ W,
             const float* __restrict__ bias, float* __restrict__ out)
{
    __shared__ __align__(16) float sA[TKK][SP];   // [k][m]
    __shared__ __align__(16) float sB[TKK][SP];   // [k][n]

    const int tid = threadIdx.x;
    const int tx = tid & 15;               // n group (8 cols)
    const int ty = tid >> 4;               // m group (8 rows)
    const int m0 = blockIdx.x * TM;
    const int n0 = blockIdx.y * TN;

    // Load mapping: 512 float4 per operand tile, 2 per thread.
    const int i0 = tid * 2, i1 = tid * 2 + 1;
    const int ar  = i0 >> 2;               // 0..127 (same for i1)
    const int ak0 = (i0 & 3) << 2;         // {0,8}
    const int ak1 = (i1 & 3) << 2;         // {4,12}
    const int bk0 = i0 >> 5, bc0 = (i0 & 31) << 2;
    const int bk1 = i1 >> 5, bc1 = (i1 & 31) << 2;

    u64 acc[8][4];
    #pragma unroll
    for (int i = 0; i < 8; i++)
        #pragma unroll
        for (int j = 0; j < 4; j++) acc[i][j] = 0ull;

    // Prefetch first K-tile
    float4 pa0 = *(const float4*)(A + (size_t)(m0 + ar) * DD + ak0);
    float4 pa1 = *(const float4*)(A + (size_t)(m0 + ar) * DD + ak1);
    float4 pb0 = *(const float4*)(W + (size_t)bk0 * DD + n0 + bc0);
    float4 pb1 = *(const float4*)(W + (size_t)bk1 * DD + n0 + bc1);

    for (int kt = 0; kt < NKT; kt++) {
        sA[ak0 + 0][ar] = pa0.x; sA[ak0 + 1][ar] = pa0.y;
        sA[ak0 + 2][ar] = pa0.z; sA[ak0 + 3][ar] = pa0.w;
        sA[ak1 + 0][ar] = pa1.x; sA[ak1 + 1][ar] = pa1.y;
        sA[ak1 + 2][ar] = pa1.z; sA[ak1 + 3][ar] = pa1.w;
        *(float4*)&sB[bk0][bc0] = pb0;
        *(float4*)&sB[bk1][bc1] = pb1;
        __syncthreads();

        if (kt + 1 < NKT) {
            const int k0 = (kt + 1) * TKK;
            pa0 = *(const float4*)(A + (size_t)(m0 + ar) * DD + k0 + ak0);
            pa1 = *(const float4*)(A + (size_t)(m0 + ar) * DD + k0 + ak1);
            pb0 = *(const float4*)(W + (size_t)(k0 + bk0) * DD + n0 + bc0);
            pb1 = *(const float4*)(W + (size_t)(k0 + bk1) * DD + n0 + bc1);
        }

        #pragma unroll
        for (int kk = 0; kk < TKK; kk++) {
            float4 a0 = *(float4*)&sA[kk][ty * 8];
            float4 a1 = *(float4*)&sA[kk][ty * 8 + 4];
            ulonglong2 b0 = *(ulonglong2*)&sB[kk][tx * 8];
            ulonglong2 b1 = *(ulonglong2*)&sB[kk][tx * 8 + 4];
            u64 bp[4] = { b0.x, b0.y, b1.x, b1.y };
            float av[8] = { a0.x, a0.y, a0.z, a0.w, a1.x, a1.y, a1.z, a1.w };
            #pragma unroll
            for (int i = 0; i < 8; i++) {
                u64 as = pk2(av[i], av[i]);
                #pragma unroll
                for (int j = 0; j < 4; j++) fma2(acc[i][j], as, bp[j]);
            }
        }
        __syncthreads();
    }

    // Epilogue: unpack pairs, add bias, coalesced stores
    const float4 bv0 = *(const float4*)(bias + n0 + tx * 8);
    const float4 bv1 = *(const float4*)(bias + n0 + tx * 8 + 4);
    #pragma unroll
    for (int i = 0; i < 8; i++) {
        float2 c0 = up2(acc[i][0]), c1 = up2(acc[i][1]);
        float2 c2 = up2(acc[i][2]), c3 = up2(acc[i][3]);
        float4 o0 = make_float4(c0.x + bv0.x, c0.y + bv0.y,
                                c1.x + bv0.z, c1.y + bv0.w);
        float4 o1 = make_float4(c2.x + bv1.x, c2.y + bv1.y,
                                c3.x + bv1.z, c3.y + bv1.w);
        float* dst = out + (size_t)(m0 + ty * 8 + i) * DD + n0 + tx * 8;
        *(float4*)dst = o0;
        *(float4*)(dst + 4) = o1;
    }
}

// ---------------------------------------------------------------------------
// FFMA2 flash attention, causal, fp32.
// 128(q) x 64(k) tiles, 256 threads (16x16), 8x4 microtile.
// Accumulators are f32x2 pairs along Q rows (natural from transposed smem).
// ---------------------------------------------------------------------------
#define AQ 128
#define AK 64
#define QP 132
#define KP 68
#define ATTN_SMEM ((64*QP + 2*64*KP + 64*QP) * 4)   // 102400 B

__global__ __launch_bounds__(256, 2)
void attn_f2(const float* __restrict__ Q, const float* __restrict__ K,
             const float* __restrict__ V, float* __restrict__ Oo)
{
    extern __shared__ __align__(16) float sm[];
    float (*sQt)[QP] = (float(*)[QP])(sm);                         // [d][qrow]
    float (*sKt)[KP] = (float(*)[KP])(sm + 64 * QP);               // [d][kcol]
    float (*sV )[KP] = (float(*)[KP])(sm + 64 * QP + 64 * KP);     // [k][d]
    float (*sPt)[QP] = (float(*)[QP])(sm + 64 * QP + 2 * 64 * KP); // [k][qrow]

    const int tid = threadIdx.x;
    const int tx = tid & 15;               // k-col / d group (4)
    const int ty = tid >> 4;               // q-row group (8)
    const int qt = (SS / AQ - 1) - blockIdx.x;   // heavy tiles first
    const int bh = blockIdx.y;
    const int b_ = bh / HH, h_ = bh % HH;

    const float* Qb = Q + (size_t)b_ * SS * DD + h_ * HDIM;
    const float* Kb = K + (size_t)b_ * SS * DD + h_ * HDIM;
    const float* Vb = V + (size_t)b_ * SS * DD + h_ * HDIM;

    // Load Q tile transposed: sQt[d][row], 128 rows
    #pragma unroll
    for (int l = 0; l < 8; l++) {
        const int idx = tid + l * 256;
        const int r = idx >> 4, d0 = (idx & 15) << 2;
        float4 v4 = *(const float4*)(Qb + (size_t)(qt * AQ + r) * DD + d0);
        sQt[d0 + 0][r] = v4.x; sQt[d0 + 1][r] = v4.y;
        sQt[d0 + 2][r] = v4.z; sQt[d0 + 3][r] = v4.w;
    }

    float mrow[8], lrow[8];
    u64 o2[4][4];
    #pragma unroll
    for (int i = 0; i < 8; i++) { mrow[i] = -1e30f; lrow[i] = 0.0f; }
    #pragma unroll
    for (int ip = 0; ip < 4; ip++)
        #pragma unroll
        for (int j = 0; j < 4; j++) o2[ip][j] = 0ull;

    const int njt = 2 * qt + 2;
    for (int jt = 0; jt < njt; jt++) {
        __syncthreads();
        // Load K transposed + V direct (64 rows each)
        #pragma unroll
        for (int l = 0; l < 4; l++) {
            const int idx = tid + l * 256;
            const int r = idx >> 4, d0 = (idx & 15) << 2;
            float4 kv = *(const float4*)(Kb + (size_t)(jt * AK + r) * DD + d0);
            sKt[d0 + 0][r] = kv.x; sKt[d0 + 1][r] = kv.y;
            sKt[d0 + 2][r] = kv.z; sKt[d0 + 3][r] = kv.w;
            *(float4*)&sV[r][d0] =
                *(const float4*)(Vb + (size_t)(jt * AK + r) * DD + d0);
        }
        __syncthreads();

        // Scores: sc2[ip][j] = pair of rows (2ip,2ip+1) vs col tx*4+j
        u64 sc2[4][4];
        #pragma unroll
        for (int ip = 0; ip < 4; ip++)
            #pragma unroll
            for (int j = 0; j < 4; j++) sc2[ip][j] = 0ull;

        #pragma unroll 8
        for (int dd = 0; dd < 64; dd++) {
            ulonglong2 qa = *(ulonglong2*)&sQt[dd][ty * 8];
            ulonglong2 qb = *(ulonglong2*)&sQt[dd][ty * 8 + 4];
            u64 ap[4] = { qa.x, qa.y, qb.x, qb.y };
            float4 kv = *(float4*)&sKt[dd][tx * 4];
            float kr[4] = { kv.x, kv.y, kv.z, kv.w };
            #pragma unroll
            for (int j = 0; j < 4; j++) {
                u64 ks = pk2(kr[j], kr[j]);
                #pragma unroll
                for (int ip = 0; ip < 4; ip++) fma2(sc2[ip][j], ap[ip], ks);
            }
        }

        const bool tail = (jt >= 2 * qt);

        #pragma unroll
        for (int ip = 0; ip < 4; ip++) {
            float v0[4], v1[4];
            #pragma unroll
            for (int j = 0; j < 4; j++) {
                float2 c = up2(sc2[ip][j]);
                v0[j] = c.x * 0.125f;
                v1[j] = c.y * 0.125f;
            }
            if (tail) {
                const int q0 = qt * AQ + ty * 8 + 2 * ip;
                #pragma unroll
                for (int j = 0; j < 4; j++) {
                    const int kg = jt * AK + tx * 4 + j;
                    if (kg > q0)     v0[j] = -1e30f;
                    if (kg > q0 + 1) v1[j] = -1e30f;
                }
            }
            float corr01[2];
            #pragma unroll
            for (int s = 0; s < 2; s++) {
                float* v = s ? v1 : v0;
                const int row = 2 * ip + s;
                float tm = fmaxf(fmaxf(v[0], v[1]), fmaxf(v[2], v[3]));
                #pragma unroll
                for (int off = 8; off; off >>= 1)
                    tm = fmaxf(tm, __shfl_xor_sync(0xffffffffu, tm, off));
                const float nm = fmaxf(mrow[row], tm);
                const float corr = __expf(mrow[row] - nm);
                float p[4], ps = 0.0f;
                #pragma unroll
                for (int j = 0; j < 4; j++) { p[j] = __expf(v[j] - nm); ps += p[j]; }
                #pragma unroll
                for (int off = 8; off; off >>= 1)
                    ps += __shfl_xor_sync(0xffffffffu, ps, off);
                lrow[row] = lrow[row] * corr + ps;
                mrow[row] = nm;
                corr01[s] = corr;
                #pragma unroll
                for (int j = 0; j < 4; j++)
                    sPt[tx * 4 + j][ty * 8 + row] = p[j];
            }
            const u64 c2 = pk2(corr01[0], corr01[1]);
            #pragma unroll
            for (int j = 0; j < 4; j++) mul2(o2[ip][j], c2);
        }
        __syncthreads();

        // O += P @ V
        #pragma unroll 8
        for (int kk = 0; kk < 64; kk++) {
            ulonglong2 pa = *(ulonglong2*)&sPt[kk][ty * 8];
            ulonglong2 pb = *(ulonglong2*)&sPt[kk][ty * 8 + 4];
            u64 ap[4] = { pa.x, pa.y, pb.x, pb.y };
            float4 vv = *(float4*)&sV[kk][tx * 4];
            float vr[4] = { vv.x, vv.y, vv.z, vv.w };
            #pragma unroll
            for (int j = 0; j < 4; j++) {
                u64 vs = pk2(vr[j], vr[j]);
                #pragma unroll
                for (int ip = 0; ip < 4; ip++) fma2(o2[ip][j], ap[ip], vs);
            }
        }
    }

    // Epilogue: normalize, write [b,s,h*64+d]
    #pragma unroll
    for (int ip = 0; ip < 4; ip++) {
        const int r0 = qt * AQ + ty * 8 + 2 * ip;
        const float inv0 = 1.0f / lrow[2 * ip];
        const float inv1 = 1.0f / lrow[2 * ip + 1];
        float2 c0 = up2(o2[ip][0]), c1 = up2(o2[ip][1]);
        float2 c2 = up2(o2[ip][2]), c3 = up2(o2[ip][3]);
        float4 r0v = make_float4(c0.x * inv0, c1.x * inv0, c2.x * inv0, c3.x * inv0);
        float4 r1v = make_float4(c0.y * inv1, c1.y * inv1, c2.y * inv1, c3.y * inv1);
        *(float4*)(Oo + ((size_t)(b_ * SS + r0)) * DD + h_ * HDIM + tx * 4) = r0v;
        *(float4*)(Oo + ((size_t)(b_ * SS + r0 + 1)) * DD + h_ * HDIM + tx * 4) = r1v;
    }
}

// ---------------------------------------------------------------------------
// Launch
// ---------------------------------------------------------------------------
extern "C" void kernel_launch(void* const* d_in, const int* in_sizes, int n_in,
                              void* d_out, int out_size)
{
    (void)n_in; (void)in_sizes; (void)out_size;

    const float* x  = (const float*)d_in[0];
    const float* wq = (const float*)d_in[2];
    const float* bq = (const float*)d_in[3];
    const float* wk = (const float*)d_in[4];
    const float* bk = (const float*)d_in[5];
    const float* wv = (const float*)d_in[6];
    const float* bv = (const float*)d_in[7];
    const float* wo = (const float*)d_in[8];
    const float* bo = (const float*)d_in[9];
    float* out = (float*)d_out;

    static float *q = nullptr, *k, *v, *att;
    if (!q) {
        cudaGetSymbolAddress((void**)&q,   g_q);
        cudaGetSymbolAddress((void**)&k,   g_k);
        cudaGetSymbolAddress((void**)&v,   g_v);
        cudaGetSymbolAddress((void**)&att, g_att);
        cudaFuncSetAttribute(attn_f2,
            cudaFuncAttributeMaxDynamicSharedMemorySize, ATTN_SMEM);
    }

    dim3 gg(NT / TM, DD / TN);    // 32 x 6
    gemm_f2<<<gg, 256>>>(x, wq, bq, q);
    gemm_f2<<<gg, 256>>>(x, wk, bk, k);
    gemm_f2<<<gg, 256>>>(x, wv, bv, v);

    dim3 ag(SS / AQ, NBH);        // 16 x 24
    attn_f2<<<ag, 256, ATTN_SMEM>>>(q, k, v, att);

    gemm_f2<<<gg, 256>>>(att, wo, bo, out);
}

// round 6
// speedup vs baseline: 1.1603x; 1.1603x over previous
#include <cuda_runtime.h>
#include <math.h>
#include <stdint.h>

// Problem constants
#define BB 2
#define SS 2048
#define DD 768
#define HH 12
#define HDIM 64
#define NT (BB*SS)      // 4096 tokens
#define NBH (BB*HH)     // 24

typedef unsigned long long u64;

// ---------------------------------------------------------------------------
// f32x2 packed helpers
// ---------------------------------------------------------------------------
__device__ __forceinline__ u64 pk2(float lo, float hi) {
    u64 r; asm("mov.b64 %0, {%1, %2};" : "=l"(r) : "f"(lo), "f"(hi)); return r;
}
__device__ __forceinline__ float2 up2(u64 v) {
    float lo, hi; asm("mov.b64 {%0, %1}, %2;" : "=f"(lo), "=f"(hi) : "l"(v));
    return make_float2(lo, hi);
}
__device__ __forceinline__ void fma2(u64& d, u64 a, u64 b) {
    asm("fma.rn.f32x2 %0, %1, %2, %0;" : "+l"(d) : "l"(a), "l"(b));
}
__device__ __forceinline__ void mul2(u64& d, u64 a) {
    asm("mul.rn.f32x2 %0, %0, %1;" : "+l"(d) : "l"(a));
}

// ---------------------------------------------------------------------------
// Device scratch
// ---------------------------------------------------------------------------
__device__ float g_q[(size_t)NT * DD];        // [b,s,d]
__device__ float g_k[(size_t)NT * DD];
__device__ float g_v[(size_t)NT * DD];
__device__ float g_att[(size_t)NT * DD];

// ---------------------------------------------------------------------------
// FFMA2 GEMM (fused-3): out_sel[m,n] = sum_k A[m,k]*W_sel[k,n] + b_sel[n]
// grid.y = 3*nbn (or nbn with identical ptrs). sel = blockIdx.y / nbn.
// CTA tile 128x128, K-tile 16, 256 threads, 8x8 microtile, double-buffered.
// ---------------------------------------------------------------------------
#define TM 128
#define TN 128
#define TKK 16
#define SP 132
#define NKT (DD / TKK)         // 48
#define NBN (DD / TN)          // 6

__global__ __launch_bounds__(256, 2)
void gemm3_f2(const float* __restrict__ A,
              const float* __restrict__ w0, const float* __restrict__ w1,
              const float* __restrict__ w2,
              const float* __restrict__ b0, const float* __restrict__ b1,
              const float* __restrict__ b2,
              float* __restrict__ o0, float* __restrict__ o1,
              float* __restrict__ o2)
{
    __shared__ __align__(16) float sA[2][TKK][SP];
    __shared__ __align__(16) float sB[2][TKK][SP];

    const int sel = blockIdx.y / NBN;
    const float* W    = (sel == 0) ? w0 : (sel == 1) ? w1 : w2;
    const float* bias = (sel == 0) ? b0 : (sel == 1) ? b1 : b2;
    float* out        = (sel == 0) ? o0 : (sel == 1) ? o1 : o2;

    const int tid = threadIdx.x;
    const int tx = tid & 15;               // n group (8 cols)
    const int ty = tid >> 4;               // m group (8 rows)
    const int m0 = blockIdx.x * TM;
    const int n0 = (blockIdx.y % NBN) * TN;

    // Load mapping: 512 float4 per operand tile, 2 per thread.
    const int i0 = tid * 2, i1 = tid * 2 + 1;
    const int ar  = i0 >> 2;
    const int ak0 = (i0 & 3) << 2;         // {0,8}
    const int ak1 = (i1 & 3) << 2;         // {4,12}
    const int bk0 = i0 >> 5, bc0 = (i0 & 31) << 2;
    const int bk1 = i1 >> 5, bc1 = (i1 & 31) << 2;

    u64 acc[8][4];
    #pragma unroll
    for (int i = 0; i < 8; i++)
        #pragma unroll
        for (int j = 0; j < 4; j++) acc[i][j] = 0ull;

    // Prefetch k-tile 0 and store to stage 0
    float4 pa0 = *(const float4*)(A + (size_t)(m0 + ar) * DD + ak0);
    float4 pa1 = *(const float4*)(A + (size_t)(m0 + ar) * DD + ak1);
    float4 pb0 = *(const float4*)(W + (size_t)bk0 * DD + n0 + bc0);
    float4 pb1 = *(const float4*)(W + (size_t)bk1 * DD + n0 + bc1);
    sA[0][ak0 + 0][ar] = pa0.x; sA[0][ak0 + 1][ar] = pa0.y;
    sA[0][ak0 + 2][ar] = pa0.z; sA[0][ak0 + 3][ar] = pa0.w;
    sA[0][ak1 + 0][ar] = pa1.x; sA[0][ak1 + 1][ar] = pa1.y;
    sA[0][ak1 + 2][ar] = pa1.z; sA[0][ak1 + 3][ar] = pa1.w;
    *(float4*)&sB[0][bk0][bc0] = pb0;
    *(float4*)&sB[0][bk1][bc1] = pb1;

    for (int kt = 0; kt < NKT; kt++) {
        const int cur = kt & 1;
        // Prefetch next k-tile (global -> regs) before the barrier
        if (kt + 1 < NKT) {
            const int k0 = (kt + 1) * TKK;
            pa0 = *(const float4*)(A + (size_t)(m0 + ar) * DD + k0 + ak0);
            pa1 = *(const float4*)(A + (size_t)(m0 + ar) * DD + k0 + ak1);
            pb0 = *(const float4*)(W + (size_t)(k0 + bk0) * DD + n0 + bc0);
            pb1 = *(const float4*)(W + (size_t)(k0 + bk1) * DD + n0 + bc1);
        }
        __syncthreads();

        #pragma unroll
        for (int kk = 0; kk < TKK; kk++) {
            float4 a0 = *(float4*)&sA[cur][kk][ty * 8];
            float4 a1 = *(float4*)&sA[cur][kk][ty * 8 + 4];
            ulonglong2 bq0 = *(ulonglong2*)&sB[cur][kk][tx * 8];
            ulonglong2 bq1 = *(ulonglong2*)&sB[cur][kk][tx * 8 + 4];
            u64 bp[4] = { bq0.x, bq0.y, bq1.x, bq1.y };
            float av[8] = { a0.x, a0.y, a0.z, a0.w, a1.x, a1.y, a1.z, a1.w };
            #pragma unroll
            for (int i = 0; i < 8; i++) {
                u64 as = pk2(av[i], av[i]);
                #pragma unroll
                for (int j = 0; j < 4; j++) fma2(acc[i][j], as, bp[j]);
            }
        }

        // Store prefetched tile into the other stage (no barrier needed here)
        if (kt + 1 < NKT) {
            const int nxt = cur ^ 1;
            sA[nxt][ak0 + 0][ar] = pa0.x; sA[nxt][ak0 + 1][ar] = pa0.y;
            sA[nxt][ak0 + 2][ar] = pa0.z; sA[nxt][ak0 + 3][ar] = pa0.w;
            sA[nxt][ak1 + 0][ar] = pa1.x; sA[nxt][ak1 + 1][ar] = pa1.y;
            sA[nxt][ak1 + 2][ar] = pa1.z; sA[nxt][ak1 + 3][ar] = pa1.w;
            *(float4*)&sB[nxt][bk0][bc0] = pb0;
            *(float4*)&sB[nxt][bk1][bc1] = pb1;
        }
    }

    // Epilogue
    const float4 bv0 = *(const float4*)(bias + n0 + tx * 8);
    const float4 bv1 = *(const float4*)(bias + n0 + tx * 8 + 4);
    #pragma unroll
    for (int i = 0; i < 8; i++) {
        float2 c0 = up2(acc[i][0]), c1 = up2(acc[i][1]);
        float2 c2 = up2(acc[i][2]), c3 = up2(acc[i][3]);
        float4 q0 = make_float4(c0.x + bv0.x, c0.y + bv0.y,
                                c1.x + bv0.z, c1.y + bv0.w);
        float4 q1 = make_float4(c2.x + bv1.x, c2.y + bv1.y,
                                c3.x + bv1.z, c3.y + bv1.w);
        float* dst = out + (size_t)(m0 + ty * 8 + i) * DD + n0 + tx * 8;
        *(float4*)dst = q0;
        *(float4*)(dst + 4) = q1;
    }
}

// ---------------------------------------------------------------------------
// FFMA2 flash attention, causal, fp32 (unchanged from round 5).
// ---------------------------------------------------------------------------
#define AQ 128
#define AK 64
#define QP 132
#define KP 68
#define ATTN_SMEM ((64*QP + 2*64*KP + 64*QP) * 4)   // 102400 B

__global__ __launch_bounds__(256, 2)
void attn_f2(const float* __restrict__ Q, const float* __restrict__ K,
             const float* __restrict__ V, float* __restrict__ Oo)
{
    extern __shared__ __align__(16) float sm[];
    float (*sQt)[QP] = (float(*)[QP])(sm);                         // [d][qrow]
    float (*sKt)[KP] = (float(*)[KP])(sm + 64 * QP);               // [d][kcol]
    float (*sV )[KP] = (float(*)[KP])(sm + 64 * QP + 64 * KP);     // [k][d]
    float (*sPt)[QP] = (float(*)[QP])(sm + 64 * QP + 2 * 64 * KP); // [k][qrow]

    const int tid = threadIdx.x;
    const int tx = tid & 15;
    const int ty = tid >> 4;
    const int qt = (SS / AQ - 1) - blockIdx.x;   // heavy tiles first
    const int bh = blockIdx.y;
    const int b_ = bh / HH, h_ = bh % HH;

    const float* Qb = Q + (size_t)b_ * SS * DD + h_ * HDIM;
    const float* Kb = K + (size_t)b_ * SS * DD + h_ * HDIM;
    const float* Vb = V + (size_t)b_ * SS * DD + h_ * HDIM;

    #pragma unroll
    for (int l = 0; l < 8; l++) {
        const int idx = tid + l * 256;
        const int r = idx >> 4, d0 = (idx & 15) << 2;
        float4 v4 = *(const float4*)(Qb + (size_t)(qt * AQ + r) * DD + d0);
        sQt[d0 + 0][r] = v4.x; sQt[d0 + 1][r] = v4.y;
        sQt[d0 + 2][r] = v4.z; sQt[d0 + 3][r] = v4.w;
    }

    float mrow[8], lrow[8];
    u64 o2[4][4];
    #pragma unroll
    for (int i = 0; i < 8; i++) { mrow[i] = -1e30f; lrow[i] = 0.0f; }
    #pragma unroll
    for (int ip = 0; ip < 4; ip++)
        #pragma unroll
        for (int j = 0; j < 4; j++) o2[ip][j] = 0ull;

    const int njt = 2 * qt + 2;
    for (int jt = 0; jt < njt; jt++) {
        __syncthreads();
        #pragma unroll
        for (int l = 0; l < 4; l++) {
            const int idx = tid + l * 256;
            const int r = idx >> 4, d0 = (idx & 15) << 2;
            float4 kv = *(const float4*)(Kb + (size_t)(jt * AK + r) * DD + d0);
            sKt[d0 + 0][r] = kv.x; sKt[d0 + 1][r] = kv.y;
            sKt[d0 + 2][r] = kv.z; sKt[d0 + 3][r] = kv.w;
            *(float4*)&sV[r][d0] =
                *(const float4*)(Vb + (size_t)(jt * AK + r) * DD + d0);
        }
        __syncthreads();

        u64 sc2[4][4];
        #pragma unroll
        for (int ip = 0; ip < 4; ip++)
            #pragma unroll
            for (int j = 0; j < 4; j++) sc2[ip][j] = 0ull;

        #pragma unroll 8
        for (int dd = 0; dd < 64; dd++) {
            ulonglong2 qa = *(ulonglong2*)&sQt[dd][ty * 8];
            ulonglong2 qb = *(ulonglong2*)&sQt[dd][ty * 8 + 4];
            u64 ap[4] = { qa.x, qa.y, qb.x, qb.y };
            float4 kv = *(float4*)&sKt[dd][tx * 4];
            float kr[4] = { kv.x, kv.y, kv.z, kv.w };
            #pragma unroll
            for (int j = 0; j < 4; j++) {
                u64 ks = pk2(kr[j], kr[j]);
                #pragma unroll
                for (int ip = 0; ip < 4; ip++) fma2(sc2[ip][j], ap[ip], ks);
            }
        }

        const bool tail = (jt >= 2 * qt);

        #pragma unroll
        for (int ip = 0; ip < 4; ip++) {
            float v0[4], v1[4];
            #pragma unroll
            for (int j = 0; j < 4; j++) {
                float2 c = up2(sc2[ip][j]);
                v0[j] = c.x * 0.125f;
                v1[j] = c.y * 0.125f;
            }
            if (tail) {
                const int q0 = qt * AQ + ty * 8 + 2 * ip;
                #pragma unroll
                for (int j = 0; j < 4; j++) {
                    const int kg = jt * AK + tx * 4 + j;
                    if (kg > q0)     v0[j] = -1e30f;
                    if (kg > q0 + 1) v1[j] = -1e30f;
                }
            }
            float corr01[2];
            #pragma unroll
            for (int s = 0; s < 2; s++) {
                float* v = s ? v1 : v0;
                const int row = 2 * ip + s;
                float tm = fmaxf(fmaxf(v[0], v[1]), fmaxf(v[2], v[3]));
                #pragma unroll
                for (int off = 8; off; off >>= 1)
                    tm = fmaxf(tm, __shfl_xor_sync(0xffffffffu, tm, off));
                const float nm = fmaxf(mrow[row], tm);
                const float corr = __expf(mrow[row] - nm);
                float p[4], ps = 0.0f;
                #pragma unroll
                for (int j = 0; j < 4; j++) { p[j] = __expf(v[j] - nm); ps += p[j]; }
                #pragma unroll
                for (int off = 8; off; off >>= 1)
                    ps += __shfl_xor_sync(0xffffffffu, ps, off);
                lrow[row] = lrow[row] * corr + ps;
                mrow[row] = nm;
                corr01[s] = corr;
                #pragma unroll
                for (int j = 0; j < 4; j++)
                    sPt[tx * 4 + j][ty * 8 + row] = p[j];
            }
            const u64 c2 = pk2(corr01[0], corr01[1]);
            #pragma unroll
            for (int j = 0; j < 4; j++) mul2(o2[ip][j], c2);
        }
        __syncthreads();

        #pragma unroll 8
        for (int kk = 0; kk < 64; kk++) {
            ulonglong2 pa = *(ulonglong2*)&sPt[kk][ty * 8];
            ulonglong2 pb = *(ulonglong2*)&sPt[kk][ty * 8 + 4];
            u64 ap[4] = { pa.x, pa.y, pb.x, pb.y };
            float4 vv = *(float4*)&sV[kk][tx * 4];
            float vr[4] = { vv.x, vv.y, vv.z, vv.w };
            #pragma unroll
            for (int j = 0; j < 4; j++) {
                u64 vs = pk2(vr[j], vr[j]);
                #pragma unroll
                for (int ip = 0; ip < 4; ip++) fma2(o2[ip][j], ap[ip], vs);
            }
        }
    }

    #pragma unroll
    for (int ip = 0; ip < 4; ip++) {
        const int r0 = qt * AQ + ty * 8 + 2 * ip;
        const float inv0 = 1.0f / lrow[2 * ip];
        const float inv1 = 1.0f / lrow[2 * ip + 1];
        float2 c0 = up2(o2[ip][0]), c1 = up2(o2[ip][1]);
        float2 c2 = up2(o2[ip][2]), c3 = up2(o2[ip][3]);
        float4 r0v = make_float4(c0.x * inv0, c1.x * inv0, c2.x * inv0, c3.x * inv0);
        float4 r1v = make_float4(c0.y * inv1, c1.y * inv1, c2.y * inv1, c3.y * inv1);
        *(float4*)(Oo + ((size_t)(b_ * SS + r0)) * DD + h_ * HDIM + tx * 4) = r0v;
        *(float4*)(Oo + ((size_t)(b_ * SS + r0 + 1)) * DD + h_ * HDIM + tx * 4) = r1v;
    }
}

// ---------------------------------------------------------------------------
// Launch
// ---------------------------------------------------------------------------
extern "C" void kernel_launch(void* const* d_in, const int* in_sizes, int n_in,
                              void* d_out, int out_size)
{
    (void)n_in; (void)in_sizes; (void)out_size;

    const float* x  = (const float*)d_in[0];
    const float* wq = (const float*)d_in[2];
    const float* bq = (const float*)d_in[3];
    const float* wk = (const float*)d_in[4];
    const float* bk = (const float*)d_in[5];
    const float* wv = (const float*)d_in[6];
    const float* bv = (const float*)d_in[7];
    const float* wo = (const float*)d_in[8];
    const float* bo = (const float*)d_in[9];
    float* out = (float*)d_out;

    static float *q = nullptr, *k, *v, *att;
    if (!q) {
        cudaGetSymbolAddress((void**)&q,   g_q);
        cudaGetSymbolAddress((void**)&k,   g_k);
        cudaGetSymbolAddress((void**)&v,   g_v);
        cudaGetSymbolAddress((void**)&att, g_att);
        cudaFuncSetAttribute(attn_f2,
            cudaFuncAttributeMaxDynamicSharedMemorySize, ATTN_SMEM);
    }

    // Fused QKV projection: 32 x 18 = 576 CTAs (full chip)
    dim3 gq(NT / TM, 3 * NBN);
    gemm3_f2<<<gq, 256>>>(x, wq, wk, wv, bq, bk, bv, q, k, v);

    // Attention
    dim3 ag(SS / AQ, NBH);        // 16 x 24
    attn_f2<<<ag, 256, ATTN_SMEM>>>(q, k, v, att);

    // Output projection (same kernel, all selectors identical)
    dim3 go(NT / TM, NBN);
    gemm3_f2<<<go, 256>>>(att, wo, wo, wo, bo, bo, bo, out, out, out);
}